// round 11
// baseline (speedup 1.0000x reference)
#include <cuda_runtime.h>
#include <cstdint>

// Problem constants
#define IDIM   32
#define MDIM   16
#define DDIM   48
#define NQ     64
#define NP1    65
#define QDIM   256
#define NBT    8
#define NPIX   524288
#define TPB    128
#define PPB    128
#define NBLK   (NPIX / PPB)   // 4096
#define ACC_STRIDE 52

// MMA tiling: D[128,48] = A[128,64] @ B[64,48]; m16n8k8 tf32 (A 1-pass, B hi+lo)
#define NI 6
#define KI 8

// B fragment image: [pass(2)][ni(6)][ki(8)][lane(32)][slot(2)] floats
#define BF_FLOATS (2 * NI * KI * 64)       // 6144
#define BF_BYTES  (BF_FLOATS * 4)          // 24576

#define FG_STRIDE 68                       // 68 mod 32 == 4 -> conflict-free A loads
#define FG_BYTES  (PPB * FG_STRIDE * 4)    // 34816
#define S_B_OFF   0
#define S_FG_OFF  BF_BYTES                 // 24576
#define S_BG_OFF  (S_FG_OFF + FG_BYTES)    // 59392
#define SMEM_BYTES (S_BG_OFF + PPB * 4)    // 59904 -> 3 blocks/SM

#define AP_WORDS  (PPB * NP1)              // 8320
#define AP_VEC4   (AP_WORDS / 4)           // 2080

__device__ __align__(16) float g_Bf[NBT * BF_FLOATS];

__device__ __forceinline__ uint32_t f2tf32(float x) {
    uint32_t r;
    asm("cvt.rna.tf32.f32 %0, %1;" : "=r"(r) : "f"(x));
    return r;
}

// ---------------------------------------------------------------------------
// Kernel 1: query projection -> B fragment image (hi/lo split). 4-way k-split.
// Block r = bt*64 + q; 256 threads: h = tid>>6 (k-chunk), d = tid&63.
// ---------------------------------------------------------------------------
__global__ void __launch_bounds__(256)
qproj_kernel(const float* __restrict__ qf,
             const float* __restrict__ Wi,
             const float* __restrict__ bi,
             const float* __restrict__ Wm,
             const float* __restrict__ bm) {
    const int r  = blockIdx.x;
    const int bt = r >> 6;
    const int q  = r & 63;
    __shared__ float s_q[QDIM];
    __shared__ float s_part[3][DDIM];
    s_q[threadIdx.x] = qf[(size_t)r * QDIM + threadIdx.x];
    __syncthreads();

    const int h = threadIdx.x >> 6;
    const int d = threadIdx.x & 63;

    float partial = 0.f;
    if (d < DDIM) {
        const int k0 = h * 64;
        if (d < IDIM) {
            #pragma unroll 8
            for (int k = 0; k < 64; k++) partial += s_q[k0 + k] * Wi[(k0 + k) * IDIM + d];
        } else {
            const int dm = d - IDIM;
            #pragma unroll 8
            for (int k = 0; k < 64; k++) partial += s_q[k0 + k] * Wm[(k0 + k) * MDIM + dm];
        }
        if (h > 0) s_part[h - 1][d] = partial;
    }
    __syncthreads();

    if (threadIdx.x < DDIM) {
        const float bias = (d < IDIM) ? bi[d] : bm[d - IDIM];
        float val = bias + partial + s_part[0][d] + s_part[1][d] + s_part[2][d];

        const uint32_t hi = f2tf32(val);
        const float    lf = val - __uint_as_float(hi);
        const uint32_t lo = f2tf32(lf);

        const int ni   = d >> 3;
        const int g    = d & 7;
        const int ki   = q >> 3;
        const int kl   = q & 7;
        const int tig  = kl & 3;
        const int slot = kl >> 2;
        const int lane = g * 4 + tig;

        float* dst = g_Bf + bt * BF_FLOATS;
        dst[((0 * NI + ni) * KI + ki) * 64 + lane * 2 + slot] = __uint_as_float(hi);
        dst[((1 * NI + ni) * KI + ki) * 64 + lane * 2 + slot] = __uint_as_float(lo);
    }
}

// ---------------------------------------------------------------------------
// Kernel 2: tf32 mma.sync pooling + fused refine. 128 threads / 128 pixels.
// ap restaged to stride-68 tf32 layout (conflict-free fragment loads).
// ---------------------------------------------------------------------------
__global__ void __launch_bounds__(TPB)
entity_kernel(const float* __restrict__ ia,
              const float* __restrict__ mc,
              const float* __restrict__ ap,
              const int*   __restrict__ aq,
              float*       __restrict__ out) {
    extern __shared__ __align__(1024) char smem[];
    float* s_B  = (float*)(smem + S_B_OFF);
    float* s_fg = (float*)(smem + S_FG_OFF);
    float* s_bg = (float*)(smem + S_BG_OFF);
    __shared__ __align__(8) unsigned long long tma_bar;

    const int tid  = threadIdx.x;
    const int w    = tid >> 5;
    const int lane = tid & 31;
    const int g    = lane >> 2;
    const int tig  = lane & 3;
    const int p0   = blockIdx.x * PPB;
    const int bt   = blockIdx.x >> 9;

    unsigned int mb     = (unsigned int)__cvta_generic_to_shared(&tma_bar);
    unsigned int s_base = (unsigned int)__cvta_generic_to_shared(smem);

    if (tid == 0) {
        asm volatile("mbarrier.init.shared.b64 [%0], 1;" :: "r"(mb) : "memory");
    }
    __syncthreads();
    if (tid == 0) {
        asm volatile("mbarrier.arrive.expect_tx.shared.b64 _, [%0], %1;"
                     :: "r"(mb), "r"((unsigned)BF_BYTES) : "memory");
        const void* src_b = (const void*)(g_Bf + bt * BF_FLOATS);
        asm volatile("cp.async.bulk.shared::cta.global.mbarrier::complete_tx::bytes "
                     "[%0], [%1], %2, [%3];"
                     :: "r"(s_base + S_B_OFF), "l"(src_b), "r"((unsigned)BF_BYTES),
                        "r"(mb) : "memory");
    }

    // ---- restage ap -> s_fg (tf32 bits, stride 68) + s_bg, overlapping B TMA ----
    {
        const float4* apv = (const float4*)(ap + (size_t)p0 * NP1);
        int wd  = tid * 4;
        int row = wd / NP1;
        int col = wd - row * NP1;
        #pragma unroll
        for (int it = 0; it < 17; it++) {
            const bool act = (it < 16) || (tid < AP_VEC4 - 16 * TPB);
            if (act) {
                float4 v = apv[tid + it * TPB];
                float e[4] = {v.x, v.y, v.z, v.w};
                #pragma unroll
                for (int k = 0; k < 4; k++) {
                    if (col == 0) s_bg[row] = e[k];
                    else s_fg[row * FG_STRIDE + col - 1] = __uint_as_float(f2tf32(e[k]));
                    if (++col == NP1) { col = 0; row++; }
                }
            }
            col += 53; row += 7;
            if (col >= NP1) { col -= NP1; row++; }
        }
    }
    __syncthreads();

    // wait for B (parity 0, acquire)
    {
        unsigned int done;
        asm volatile("{\n\t.reg .pred p;\n\t"
                     "mbarrier.try_wait.parity.acquire.cta.shared::cta.b64 p, [%1], 0;\n\t"
                     "selp.b32 %0, 1, 0, p;\n\t}" : "=r"(done) : "r"(mb) : "memory");
        while (!done) {
            asm volatile("{\n\t.reg .pred p;\n\t"
                         "mbarrier.try_wait.parity.acquire.cta.shared::cta.b64 p, [%1], 0, 0x989680;\n\t"
                         "selp.b32 %0, 1, 0, p;\n\t}" : "=r"(done) : "r"(mb) : "memory");
        }
    }

    // ---- MMA mainloop ----
    float c[2][NI][4];
    #pragma unroll
    for (int mi = 0; mi < 2; mi++)
        #pragma unroll
        for (int ni = 0; ni < NI; ni++)
            #pragma unroll
            for (int j = 0; j < 4; j++) c[mi][ni][j] = 0.f;

    const int r_base = w * 32 + g;
    float fs[2][2] = {{0.f, 0.f}, {0.f, 0.f}};

    #pragma unroll
    for (int ki = 0; ki < KI; ki++) {
        uint32_t ah[2][4];
        #pragma unroll
        for (int mi = 0; mi < 2; mi++) {
            const int r0 = r_base + mi * 16;
            const int q0 = ki * 8 + tig;
            #pragma unroll
            for (int j = 0; j < 4; j++) {
                const int rr = r0 + ((j & 1) ? 8 : 0);
                const int qq = q0 + ((j & 2) ? 4 : 0);
                const float x = s_fg[rr * FG_STRIDE + qq];   // conflict-free
                fs[mi][j & 1] += x;
                ah[mi][j] = __float_as_uint(x);
            }
        }
        #pragma unroll
        for (int ni = 0; ni < NI; ni++) {
            const float2 bhv = *(const float2*)(s_B + ((0 * NI + ni) * KI + ki) * 64 + lane * 2);
            const float2 blv = *(const float2*)(s_B + ((1 * NI + ni) * KI + ki) * 64 + lane * 2);
            const uint32_t bh0 = __float_as_uint(bhv.x), bh1 = __float_as_uint(bhv.y);
            const uint32_t bl0 = __float_as_uint(blv.x), bl1 = __float_as_uint(blv.y);
            #pragma unroll
            for (int mi = 0; mi < 2; mi++) {
                asm("mma.sync.aligned.m16n8k8.row.col.f32.tf32.tf32.f32 "
                    "{%0,%1,%2,%3}, {%4,%5,%6,%7}, {%8,%9}, {%0,%1,%2,%3};"
                    : "+f"(c[mi][ni][0]), "+f"(c[mi][ni][1]), "+f"(c[mi][ni][2]), "+f"(c[mi][ni][3])
                    : "r"(ah[mi][0]), "r"(ah[mi][1]), "r"(ah[mi][2]), "r"(ah[mi][3]),
                      "r"(bh0), "r"(bh1));
                asm("mma.sync.aligned.m16n8k8.row.col.f32.tf32.tf32.f32 "
                    "{%0,%1,%2,%3}, {%4,%5,%6,%7}, {%8,%9}, {%0,%1,%2,%3};"
                    : "+f"(c[mi][ni][0]), "+f"(c[mi][ni][1]), "+f"(c[mi][ni][2]), "+f"(c[mi][ni][3])
                    : "r"(ah[mi][0]), "r"(ah[mi][1]), "r"(ah[mi][2]), "r"(ah[mi][3]),
                      "r"(bl0), "r"(bl1));
            }
        }
    }

    // ---- fsum reduce over quad, scales ----
    #pragma unroll
    for (int mi = 0; mi < 2; mi++) {
        #pragma unroll
        for (int h = 0; h < 2; h++) {
            fs[mi][h] += __shfl_xor_sync(0xffffffffu, fs[mi][h], 1);
            fs[mi][h] += __shfl_xor_sync(0xffffffffu, fs[mi][h], 2);
        }
    }
    float sc0[2], sc1[2];
    #pragma unroll
    for (int mi = 0; mi < 2; mi++) {
        const int r0 = r_base + mi * 16;
        sc0[mi] = (1.f - s_bg[r0])     / fmaxf(fs[mi][0], 1e-6f);
        sc1[mi] = (1.f - s_bg[r0 + 8]) / fmaxf(fs[mi][1], 1e-6f);
    }

    __syncthreads();
    float* s_acc = s_fg;              // 128*52*4 = 26624 <= 34816
    #pragma unroll
    for (int mi = 0; mi < 2; mi++) {
        const int r0 = r_base + mi * 16;
        #pragma unroll
        for (int ni = 0; ni < NI; ni++) {
            const int col = ni * 8 + 2 * tig;
            float2 v0, v1;
            v0.x = sc0[mi] * c[mi][ni][0];
            v0.y = sc0[mi] * c[mi][ni][1];
            v1.x = sc1[mi] * c[mi][ni][2];
            v1.y = sc1[mi] * c[mi][ni][3];
            *(float2*)(s_acc + r0 * ACC_STRIDE + col)       = v0;
            *(float2*)(s_acc + (r0 + 8) * ACC_STRIDE + col) = v1;
        }
    }
    __syncthreads();

    // ---- fully coalesced epilogue ----
    out[p0 + tid] = (float)aq[p0 + tid];

    const float4* sa4 = (const float4*)s_acc;
    {
        const float4* ia4 = (const float4*)(ia + (size_t)p0 * IDIM);
        float4* o4 = (float4*)(out + (size_t)NPIX + (size_t)p0 * IDIM);
        #pragma unroll
        for (int it = 0; it < PPB * IDIM / 4 / TPB; it++) {   // 8
            const int i  = tid + it * TPB;
            const int j  = i >> 3;
            const int d4 = i & 7;
            float4 v = ia4[i];
            float4 a = sa4[j * (ACC_STRIDE / 4) + d4];
            v.x += a.x; v.y += a.y; v.z += a.z; v.w += a.w;
            o4[i] = v;
        }
    }
    {
        const float4* mc4 = (const float4*)(mc + (size_t)p0 * MDIM);
        float4* o4 = (float4*)(out + (size_t)NPIX + (size_t)NPIX * IDIM + (size_t)p0 * MDIM);
        #pragma unroll
        for (int it = 0; it < PPB * MDIM / 4 / TPB; it++) {   // 4
            const int i  = tid + it * TPB;
            const int j  = i >> 2;
            const int d4 = i & 3;
            float4 v = mc4[i];
            float4 a = sa4[j * (ACC_STRIDE / 4) + (IDIM / 4) + d4];
            v.x += a.x; v.y += a.y; v.z += a.z; v.w += a.w;
            o4[i] = v;
        }
    }
}

// ---------------------------------------------------------------------------
extern "C" void kernel_launch(void* const* d_in, const int* in_sizes, int n_in,
                              void* d_out, int out_size) {
    const float* ia = (const float*)d_in[0];
    const float* mc = (const float*)d_in[1];
    const float* qf = (const float*)d_in[2];
    const float* ap = (const float*)d_in[3];
    const int*   aq = (const int*)  d_in[4];
    const float* Wi = (const float*)d_in[5];
    const float* bi = (const float*)d_in[6];
    const float* Wm = (const float*)d_in[7];
    const float* bm = (const float*)d_in[8];

    cudaFuncSetAttribute(entity_kernel,
                         cudaFuncAttributeMaxDynamicSharedMemorySize, SMEM_BYTES);

    qproj_kernel<<<NBT * NQ, 256>>>(qf, Wi, bi, Wm, bm);
    entity_kernel<<<NBLK, TPB, SMEM_BYTES>>>(ia, mc, ap, aq, (float*)d_out);
}

// round 15
// speedup vs baseline: 1.3547x; 1.3547x over previous
#include <cuda_runtime.h>
#include <cstdint>

// Problem constants
#define IDIM   32
#define MDIM   16
#define DDIM   48
#define NQ     64
#define NP1    65
#define QDIM   256
#define NBT    8
#define NPIX   524288
#define TPB    128
#define PPB    128
#define NBLK   (NPIX / PPB)   // 4096
#define ACC_STRIDE 52

// MMA tiling: D[128,48] = A[128,64] @ B[64,48]; m16n8k8 tf32 (A 1-pass, B hi+lo)
#define NI 6
#define KI 8

// B fragment image: [pass(2)][ni(6)][ki(8)][lane(32)][slot(2)] floats
#define BF_FLOATS (2 * NI * KI * 64)       // 6144
#define BF_BYTES  (BF_FLOATS * 4)          // 24576

#define AP_BYTES  (PPB * NP1 * 4)          // 33280
#define S_B_OFF   0
#define S_AP_OFF  BF_BYTES                 // 24576
#define SMEM_BYTES (S_AP_OFF + AP_BYTES)   // 57856 -> 3 blocks/SM

__device__ __align__(16) float g_Bf[NBT * BF_FLOATS];

__device__ __forceinline__ uint32_t f2tf32(float x) {
    uint32_t r;
    asm("cvt.rna.tf32.f32 %0, %1;" : "=r"(r) : "f"(x));
    return r;
}

// ---------------------------------------------------------------------------
// Kernel 1: query projection -> B fragment image (hi/lo split). 4-way k-split.
// Block r = bt*64 + q; 256 threads: h = tid>>6 (k-chunk), d = tid&63.
// ---------------------------------------------------------------------------
__global__ void __launch_bounds__(256)
qproj_kernel(const float* __restrict__ qf,
             const float* __restrict__ Wi,
             const float* __restrict__ bi,
             const float* __restrict__ Wm,
             const float* __restrict__ bm) {
    const int r  = blockIdx.x;
    const int bt = r >> 6;
    const int q  = r & 63;
    __shared__ float s_q[QDIM];
    __shared__ float s_part[3][DDIM];
    s_q[threadIdx.x] = qf[(size_t)r * QDIM + threadIdx.x];
    __syncthreads();

    const int h = threadIdx.x >> 6;
    const int d = threadIdx.x & 63;

    float partial = 0.f;
    if (d < DDIM) {
        const int k0 = h * 64;
        if (d < IDIM) {
            #pragma unroll 8
            for (int k = 0; k < 64; k++) partial += s_q[k0 + k] * Wi[(k0 + k) * IDIM + d];
        } else {
            const int dm = d - IDIM;
            #pragma unroll 8
            for (int k = 0; k < 64; k++) partial += s_q[k0 + k] * Wm[(k0 + k) * MDIM + dm];
        }
        if (h > 0) s_part[h - 1][d] = partial;
    }
    __syncthreads();

    if (threadIdx.x < DDIM) {
        const float bias = (d < IDIM) ? bi[d] : bm[d - IDIM];
        float val = bias + partial + s_part[0][d] + s_part[1][d] + s_part[2][d];

        const uint32_t hi = f2tf32(val);
        const float    lf = val - __uint_as_float(hi);
        const uint32_t lo = f2tf32(lf);

        const int ni   = d >> 3;
        const int g    = d & 7;
        const int ki   = q >> 3;
        const int kl   = q & 7;
        const int tig  = kl & 3;
        const int slot = kl >> 2;
        const int lane = g * 4 + tig;

        float* dst = g_Bf + bt * BF_FLOATS;
        dst[((0 * NI + ni) * KI + ki) * 64 + lane * 2 + slot] = __uint_as_float(hi);
        dst[((1 * NI + ni) * KI + ki) * 64 + lane * 2 + slot] = __uint_as_float(lo);
    }
}

// ---------------------------------------------------------------------------
// Kernel 2: tf32 mma.sync pooling + fused refine. 128 threads / 128 pixels.
// MMA row m -> pixel pix = 32w + 4g + 2mi + (j&1): conflict-free A-LDS.
// ---------------------------------------------------------------------------
__global__ void __launch_bounds__(TPB)
entity_kernel(const float* __restrict__ ia,
              const float* __restrict__ mc,
              const float* __restrict__ ap,
              const int*   __restrict__ aq,
              float*       __restrict__ out) {
    extern __shared__ __align__(1024) char smem[];
    float* s_B  = (float*)(smem + S_B_OFF);
    float* s_ap = (float*)(smem + S_AP_OFF);
    __shared__ __align__(8) unsigned long long tma_bar;

    const int tid  = threadIdx.x;
    const int w    = tid >> 5;
    const int lane = tid & 31;
    const int g    = lane >> 2;
    const int tig  = lane & 3;
    const int p0   = blockIdx.x * PPB;
    const int bt   = blockIdx.x >> 9;        // 512 blocks per bt

    unsigned int mb     = (unsigned int)__cvta_generic_to_shared(&tma_bar);
    unsigned int s_base = (unsigned int)__cvta_generic_to_shared(smem);

    if (tid == 0) {
        asm volatile("mbarrier.init.shared.b64 [%0], 1;" :: "r"(mb) : "memory");
        asm volatile("mbarrier.arrive.expect_tx.shared.b64 _, [%0], %1;"
                     :: "r"(mb), "r"((unsigned)(AP_BYTES + BF_BYTES)) : "memory");
    }
    __syncthreads();
    if (tid == 0) {
        const void* src_ap = (const void*)(ap + (size_t)p0 * NP1);
        const void* src_b  = (const void*)(g_Bf + bt * BF_FLOATS);
        asm volatile("cp.async.bulk.shared::cta.global.mbarrier::complete_tx::bytes "
                     "[%0], [%1], %2, [%3];"
                     :: "r"(s_base + S_AP_OFF), "l"(src_ap), "r"((unsigned)AP_BYTES),
                        "r"(mb) : "memory");
        asm volatile("cp.async.bulk.shared::cta.global.mbarrier::complete_tx::bytes "
                     "[%0], [%1], %2, [%3];"
                     :: "r"(s_base + S_B_OFF), "l"(src_b), "r"((unsigned)BF_BYTES),
                        "r"(mb) : "memory");
    }
    // wait (parity 0, acquire)
    {
        unsigned int done;
        asm volatile("{\n\t.reg .pred p;\n\t"
                     "mbarrier.try_wait.parity.acquire.cta.shared::cta.b64 p, [%1], 0;\n\t"
                     "selp.b32 %0, 1, 0, p;\n\t}" : "=r"(done) : "r"(mb) : "memory");
        while (!done) {
            asm volatile("{\n\t.reg .pred p;\n\t"
                         "mbarrier.try_wait.parity.acquire.cta.shared::cta.b64 p, [%1], 0, 0x989680;\n\t"
                         "selp.b32 %0, 1, 0, p;\n\t}" : "=r"(done) : "r"(mb) : "memory");
        }
    }

    // ---- MMA mainloop: A single-pass tf32, B hi+lo ----
    float c[2][NI][4];
    #pragma unroll
    for (int mi = 0; mi < 2; mi++)
        #pragma unroll
        for (int ni = 0; ni < NI; ni++)
            #pragma unroll
            for (int j = 0; j < 4; j++) c[mi][ni][j] = 0.f;

    // pixel rows owned by this thread's fragments:
    // c[mi][.][0,1] -> pixA = 32w + 4g + 2mi ; c[mi][.][2,3] -> pixA + 1
    const int pix_base = w * 32 + g * 4;

    float fs[2][2] = {{0.f, 0.f}, {0.f, 0.f}};

    #pragma unroll
    for (int ki = 0; ki < KI; ki++) {
        uint32_t ah[2][4];
        #pragma unroll
        for (int mi = 0; mi < 2; mi++) {
            const int q0 = ki * 8 + tig;
            #pragma unroll
            for (int j = 0; j < 4; j++) {
                const int pix = pix_base + 2 * mi + (j & 1);
                const int qq  = q0 + ((j & 2) ? 4 : 0);
                const float x = s_ap[pix * NP1 + 1 + qq];   // bank = 4g+tig+c: conflict-free
                fs[mi][j & 1] += x;
                ah[mi][j] = f2tf32(x);
            }
        }
        #pragma unroll
        for (int ni = 0; ni < NI; ni++) {
            const float2 bhv = *(const float2*)(s_B + ((0 * NI + ni) * KI + ki) * 64 + lane * 2);
            const float2 blv = *(const float2*)(s_B + ((1 * NI + ni) * KI + ki) * 64 + lane * 2);
            const uint32_t bh0 = __float_as_uint(bhv.x), bh1 = __float_as_uint(bhv.y);
            const uint32_t bl0 = __float_as_uint(blv.x), bl1 = __float_as_uint(blv.y);
            #pragma unroll
            for (int mi = 0; mi < 2; mi++) {
                asm("mma.sync.aligned.m16n8k8.row.col.f32.tf32.tf32.f32 "
                    "{%0,%1,%2,%3}, {%4,%5,%6,%7}, {%8,%9}, {%0,%1,%2,%3};"
                    : "+f"(c[mi][ni][0]), "+f"(c[mi][ni][1]), "+f"(c[mi][ni][2]), "+f"(c[mi][ni][3])
                    : "r"(ah[mi][0]), "r"(ah[mi][1]), "r"(ah[mi][2]), "r"(ah[mi][3]),
                      "r"(bh0), "r"(bh1));
                asm("mma.sync.aligned.m16n8k8.row.col.f32.tf32.tf32.f32 "
                    "{%0,%1,%2,%3}, {%4,%5,%6,%7}, {%8,%9}, {%0,%1,%2,%3};"
                    : "+f"(c[mi][ni][0]), "+f"(c[mi][ni][1]), "+f"(c[mi][ni][2]), "+f"(c[mi][ni][3])
                    : "r"(ah[mi][0]), "r"(ah[mi][1]), "r"(ah[mi][2]), "r"(ah[mi][3]),
                      "r"(bl0), "r"(bl1));
            }
        }
    }

    // ---- fsum reduce over quad (lanes g*4 + 0..3), scales ----
    #pragma unroll
    for (int mi = 0; mi < 2; mi++) {
        #pragma unroll
        for (int h = 0; h < 2; h++) {
            fs[mi][h] += __shfl_xor_sync(0xffffffffu, fs[mi][h], 1);
            fs[mi][h] += __shfl_xor_sync(0xffffffffu, fs[mi][h], 2);
        }
    }
    float sc0[2], sc1[2];
    #pragma unroll
    for (int mi = 0; mi < 2; mi++) {
        const int pixA = pix_base + 2 * mi;
        sc0[mi] = (1.f - s_ap[pixA * NP1])       / fmaxf(fs[mi][0], 1e-6f);
        sc1[mi] = (1.f - s_ap[(pixA + 1) * NP1]) / fmaxf(fs[mi][1], 1e-6f);
    }

    __syncthreads();                  // all warps done reading s_ap / s_B
    float* s_acc = s_ap;              // 128*52*4 = 26624 <= 33280
    #pragma unroll
    for (int mi = 0; mi < 2; mi++) {
        const int pixA = pix_base + 2 * mi;
        #pragma unroll
        for (int ni = 0; ni < NI; ni++) {
            const int col = ni * 8 + 2 * tig;
            float2 v0, v1;
            v0.x = sc0[mi] * c[mi][ni][0];
            v0.y = sc0[mi] * c[mi][ni][1];
            v1.x = sc1[mi] * c[mi][ni][2];
            v1.y = sc1[mi] * c[mi][ni][3];
            *(float2*)(s_acc + pixA * ACC_STRIDE + col)       = v0;
            *(float2*)(s_acc + (pixA + 1) * ACC_STRIDE + col) = v1;
        }
    }
    __syncthreads();

    // ---- fully coalesced epilogue ----
    out[p0 + tid] = (float)aq[p0 + tid];

    const float4* sa4 = (const float4*)s_acc;
    {
        const float4* ia4 = (const float4*)(ia + (size_t)p0 * IDIM);
        float4* o4 = (float4*)(out + (size_t)NPIX + (size_t)p0 * IDIM);
        #pragma unroll
        for (int it = 0; it < PPB * IDIM / 4 / TPB; it++) {   // 8
            const int i  = tid + it * TPB;
            const int j  = i >> 3;
            const int d4 = i & 7;
            float4 v = ia4[i];
            float4 a = sa4[j * (ACC_STRIDE / 4) + d4];
            v.x += a.x; v.y += a.y; v.z += a.z; v.w += a.w;
            o4[i] = v;
        }
    }
    {
        const float4* mc4 = (const float4*)(mc + (size_t)p0 * MDIM);
        float4* o4 = (float4*)(out + (size_t)NPIX + (size_t)NPIX * IDIM + (size_t)p0 * MDIM);
        #pragma unroll
        for (int it = 0; it < PPB * MDIM / 4 / TPB; it++) {   // 4
            const int i  = tid + it * TPB;
            const int j  = i >> 2;
            const int d4 = i & 3;
            float4 v = mc4[i];
            float4 a = sa4[j * (ACC_STRIDE / 4) + (IDIM / 4) + d4];
            v.x += a.x; v.y += a.y; v.z += a.z; v.w += a.w;
            o4[i] = v;
        }
    }
}

// ---------------------------------------------------------------------------
extern "C" void kernel_launch(void* const* d_in, const int* in_sizes, int n_in,
                              void* d_out, int out_size) {
    const float* ia = (const float*)d_in[0];
    const float* mc = (const float*)d_in[1];
    const float* qf = (const float*)d_in[2];
    const float* ap = (const float*)d_in[3];
    const int*   aq = (const int*)  d_in[4];
    const float* Wi = (const float*)d_in[5];
    const float* bi = (const float*)d_in[6];
    const float* Wm = (const float*)d_in[7];
    const float* bm = (const float*)d_in[8];

    cudaFuncSetAttribute(entity_kernel,
                         cudaFuncAttributeMaxDynamicSharedMemorySize, SMEM_BYTES);

    qproj_kernel<<<NBT * NQ, 256>>>(qf, Wi, bi, Wm, bm);
    entity_kernel<<<NBLK, TPB, SMEM_BYTES>>>(ia, mc, ap, aq, (float*)d_out);
}

// round 17
// speedup vs baseline: 1.3553x; 1.0005x over previous
#include <cuda_runtime.h>
#include <cstdint>

// Problem constants
#define IDIM   32
#define MDIM   16
#define DDIM   48
#define NQ     64
#define NP1    65
#define QDIM   256
#define NBT    8
#define NPIX   524288
#define TPB    128
#define PPB    128
#define NBLK   (NPIX / PPB)   // 4096
#define ACC_STRIDE 52

// MMA tiling: D[128,48] = A[128,64] @ B[64,48]; m16n8k8 tf32 (A 1-pass, B hi+lo)
#define NI 6
#define KI 8

// B fragment image: [pass(2)][ni(6)][ki(8)][lane(32)][slot(2)] floats
#define BF_FLOATS (2 * NI * KI * 64)       // 6144
#define BF_BYTES  (BF_FLOATS * 4)          // 24576

#define AP_BYTES  (PPB * NP1 * 4)          // 33280
#define S_B_OFF   0
#define S_AP_OFF  BF_BYTES                 // 24576
#define SMEM_BYTES (S_AP_OFF + AP_BYTES)   // 57856 -> 3 blocks/SM

__device__ __align__(16) float g_Bf[NBT * BF_FLOATS];

__device__ __forceinline__ uint32_t f2tf32(float x) {
    uint32_t r;
    asm("cvt.rna.tf32.f32 %0, %1;" : "=r"(r) : "f"(x));
    return r;
}

// ---------------------------------------------------------------------------
// Kernel 1: query projection -> B fragment image (hi/lo split). 4-way k-split.
// ---------------------------------------------------------------------------
__global__ void __launch_bounds__(256)
qproj_kernel(const float* __restrict__ qf,
             const float* __restrict__ Wi,
             const float* __restrict__ bi,
             const float* __restrict__ Wm,
             const float* __restrict__ bm) {
    const int r  = blockIdx.x;
    const int bt = r >> 6;
    const int q  = r & 63;
    __shared__ float s_q[QDIM];
    __shared__ float s_part[3][DDIM];
    s_q[threadIdx.x] = qf[(size_t)r * QDIM + threadIdx.x];
    __syncthreads();

    const int h = threadIdx.x >> 6;
    const int d = threadIdx.x & 63;

    float partial = 0.f;
    if (d < DDIM) {
        const int k0 = h * 64;
        if (d < IDIM) {
            #pragma unroll 8
            for (int k = 0; k < 64; k++) partial += s_q[k0 + k] * Wi[(k0 + k) * IDIM + d];
        } else {
            const int dm = d - IDIM;
            #pragma unroll 8
            for (int k = 0; k < 64; k++) partial += s_q[k0 + k] * Wm[(k0 + k) * MDIM + dm];
        }
        if (h > 0) s_part[h - 1][d] = partial;
    }
    __syncthreads();

    if (threadIdx.x < DDIM) {
        const float bias = (d < IDIM) ? bi[d] : bm[d - IDIM];
        float val = bias + partial + s_part[0][d] + s_part[1][d] + s_part[2][d];

        const uint32_t hi = f2tf32(val);
        const float    lf = val - __uint_as_float(hi);
        const uint32_t lo = f2tf32(lf);

        const int ni   = d >> 3;
        const int g    = d & 7;
        const int ki   = q >> 3;
        const int kl   = q & 7;
        const int tig  = kl & 3;
        const int slot = kl >> 2;
        const int lane = g * 4 + tig;

        float* dst = g_Bf + bt * BF_FLOATS;
        dst[((0 * NI + ni) * KI + ki) * 64 + lane * 2 + slot] = __uint_as_float(hi);
        dst[((1 * NI + ni) * KI + ki) * 64 + lane * 2 + slot] = __uint_as_float(lo);
    }
}

// ---------------------------------------------------------------------------
// Kernel 2: tf32 mma.sync pooling + fused refine. 128 threads / 128 pixels.
// ia/mc/aq prefetched into registers at entry (overlaps TMA wait + MMA).
// ---------------------------------------------------------------------------
__global__ void __launch_bounds__(TPB, 3)
entity_kernel(const float* __restrict__ ia,
              const float* __restrict__ mc,
              const float* __restrict__ ap,
              const int*   __restrict__ aq,
              float*       __restrict__ out) {
    extern __shared__ __align__(1024) char smem[];
    float* s_B  = (float*)(smem + S_B_OFF);
    float* s_ap = (float*)(smem + S_AP_OFF);
    __shared__ __align__(8) unsigned long long tma_bar;

    const int tid  = threadIdx.x;
    const int w    = tid >> 5;
    const int lane = tid & 31;
    const int g    = lane >> 2;
    const int tig  = lane & 3;
    const int p0   = blockIdx.x * PPB;
    const int bt   = blockIdx.x >> 9;        // 512 blocks per bt

    unsigned int mb     = (unsigned int)__cvta_generic_to_shared(&tma_bar);
    unsigned int s_base = (unsigned int)__cvta_generic_to_shared(smem);

    if (tid == 0) {
        asm volatile("mbarrier.init.shared.b64 [%0], 1;" :: "r"(mb) : "memory");
        asm volatile("mbarrier.arrive.expect_tx.shared.b64 _, [%0], %1;"
                     :: "r"(mb), "r"((unsigned)(AP_BYTES + BF_BYTES)) : "memory");
    }
    __syncthreads();
    if (tid == 0) {
        const void* src_ap = (const void*)(ap + (size_t)p0 * NP1);
        const void* src_b  = (const void*)(g_Bf + bt * BF_FLOATS);
        asm volatile("cp.async.bulk.shared::cta.global.mbarrier::complete_tx::bytes "
                     "[%0], [%1], %2, [%3];"
                     :: "r"(s_base + S_AP_OFF), "l"(src_ap), "r"((unsigned)AP_BYTES),
                        "r"(mb) : "memory");
        asm volatile("cp.async.bulk.shared::cta.global.mbarrier::complete_tx::bytes "
                     "[%0], [%1], %2, [%3];"
                     :: "r"(s_base + S_B_OFF), "l"(src_b), "r"((unsigned)BF_BYTES),
                        "r"(mb) : "memory");
    }

    // ---- prefetch ia/mc/aq into registers (overlaps TMA + MMA) ----
    float4 pf_ia[8], pf_mc[4];
    {
        const float4* ia4 = (const float4*)(ia + (size_t)p0 * IDIM);
        #pragma unroll
        for (int it = 0; it < 8; it++) pf_ia[it] = ia4[tid + it * TPB];
        const float4* mc4 = (const float4*)(mc + (size_t)p0 * MDIM);
        #pragma unroll
        for (int it = 0; it < 4; it++) pf_mc[it] = mc4[tid + it * TPB];
    }
    const float aqv = (float)aq[p0 + tid];

    // wait (parity 0, acquire)
    {
        unsigned int done;
        asm volatile("{\n\t.reg .pred p;\n\t"
                     "mbarrier.try_wait.parity.acquire.cta.shared::cta.b64 p, [%1], 0;\n\t"
                     "selp.b32 %0, 1, 0, p;\n\t}" : "=r"(done) : "r"(mb) : "memory");
        while (!done) {
            asm volatile("{\n\t.reg .pred p;\n\t"
                         "mbarrier.try_wait.parity.acquire.cta.shared::cta.b64 p, [%1], 0, 0x989680;\n\t"
                         "selp.b32 %0, 1, 0, p;\n\t}" : "=r"(done) : "r"(mb) : "memory");
        }
    }

    // ---- MMA mainloop: A single-pass tf32, B hi+lo ----
    float c[2][NI][4];
    #pragma unroll
    for (int mi = 0; mi < 2; mi++)
        #pragma unroll
        for (int ni = 0; ni < NI; ni++)
            #pragma unroll
            for (int j = 0; j < 4; j++) c[mi][ni][j] = 0.f;

    // c[mi][.][0,1] -> pixA = 32w + 4g + 2mi ; c[mi][.][2,3] -> pixA + 1
    const int pix_base = w * 32 + g * 4;

    float fs[2][2] = {{0.f, 0.f}, {0.f, 0.f}};

    #pragma unroll
    for (int ki = 0; ki < KI; ki++) {
        uint32_t ah[2][4];
        #pragma unroll
        for (int mi = 0; mi < 2; mi++) {
            const int q0 = ki * 8 + tig;
            #pragma unroll
            for (int j = 0; j < 4; j++) {
                const int pix = pix_base + 2 * mi + (j & 1);
                const int qq  = q0 + ((j & 2) ? 4 : 0);
                const float x = s_ap[pix * NP1 + 1 + qq];   // conflict-free
                fs[mi][j & 1] += x;
                ah[mi][j] = f2tf32(x);
            }
        }
        #pragma unroll
        for (int ni = 0; ni < NI; ni++) {
            const float2 bhv = *(const float2*)(s_B + ((0 * NI + ni) * KI + ki) * 64 + lane * 2);
            const float2 blv = *(const float2*)(s_B + ((1 * NI + ni) * KI + ki) * 64 + lane * 2);
            const uint32_t bh0 = __float_as_uint(bhv.x), bh1 = __float_as_uint(bhv.y);
            const uint32_t bl0 = __float_as_uint(blv.x), bl1 = __float_as_uint(blv.y);
            #pragma unroll
            for (int mi = 0; mi < 2; mi++) {
                asm("mma.sync.aligned.m16n8k8.row.col.f32.tf32.tf32.f32 "
                    "{%0,%1,%2,%3}, {%4,%5,%6,%7}, {%8,%9}, {%0,%1,%2,%3};"
                    : "+f"(c[mi][ni][0]), "+f"(c[mi][ni][1]), "+f"(c[mi][ni][2]), "+f"(c[mi][ni][3])
                    : "r"(ah[mi][0]), "r"(ah[mi][1]), "r"(ah[mi][2]), "r"(ah[mi][3]),
                      "r"(bh0), "r"(bh1));
                asm("mma.sync.aligned.m16n8k8.row.col.f32.tf32.tf32.f32 "
                    "{%0,%1,%2,%3}, {%4,%5,%6,%7}, {%8,%9}, {%0,%1,%2,%3};"
                    : "+f"(c[mi][ni][0]), "+f"(c[mi][ni][1]), "+f"(c[mi][ni][2]), "+f"(c[mi][ni][3])
                    : "r"(ah[mi][0]), "r"(ah[mi][1]), "r"(ah[mi][2]), "r"(ah[mi][3]),
                      "r"(bl0), "r"(bl1));
            }
        }
    }

    // ---- fsum reduce over quad (lanes g*4 + 0..3), scales ----
    #pragma unroll
    for (int mi = 0; mi < 2; mi++) {
        #pragma unroll
        for (int h = 0; h < 2; h++) {
            fs[mi][h] += __shfl_xor_sync(0xffffffffu, fs[mi][h], 1);
            fs[mi][h] += __shfl_xor_sync(0xffffffffu, fs[mi][h], 2);
        }
    }
    float sc0[2], sc1[2];
    #pragma unroll
    for (int mi = 0; mi < 2; mi++) {
        const int pixA = pix_base + 2 * mi;
        sc0[mi] = (1.f - s_ap[pixA * NP1])       / fmaxf(fs[mi][0], 1e-6f);
        sc1[mi] = (1.f - s_ap[(pixA + 1) * NP1]) / fmaxf(fs[mi][1], 1e-6f);
    }

    __syncthreads();                  // all warps done reading s_ap / s_B
    float* s_acc = s_ap;              // 128*52*4 = 26624 <= 33280
    #pragma unroll
    for (int mi = 0; mi < 2; mi++) {
        const int pixA = pix_base + 2 * mi;
        #pragma unroll
        for (int ni = 0; ni < NI; ni++) {
            const int col = ni * 8 + 2 * tig;
            float2 v0, v1;
            v0.x = sc0[mi] * c[mi][ni][0];
            v0.y = sc0[mi] * c[mi][ni][1];
            v1.x = sc1[mi] * c[mi][ni][2];
            v1.y = sc1[mi] * c[mi][ni][3];
            *(float2*)(s_acc + pixA * ACC_STRIDE + col)       = v0;
            *(float2*)(s_acc + (pixA + 1) * ACC_STRIDE + col) = v1;
        }
    }
    __syncthreads();

    // ---- epilogue: smem + registers -> coalesced STG only ----
    out[p0 + tid] = aqv;

    const float4* sa4 = (const float4*)s_acc;
    {
        float4* o4 = (float4*)(out + (size_t)NPIX + (size_t)p0 * IDIM);
        #pragma unroll
        for (int it = 0; it < 8; it++) {
            const int i  = tid + it * TPB;
            const int j  = i >> 3;
            const int d4 = i & 7;
            float4 v = pf_ia[it];
            float4 a = sa4[j * (ACC_STRIDE / 4) + d4];
            v.x += a.x; v.y += a.y; v.z += a.z; v.w += a.w;
            o4[i] = v;
        }
    }
    {
        float4* o4 = (float4*)(out + (size_t)NPIX + (size_t)NPIX * IDIM + (size_t)p0 * MDIM);
        #pragma unroll
        for (int it = 0; it < 4; it++) {
            const int i  = tid + it * TPB;
            const int j  = i >> 2;
            const int d4 = i & 3;
            float4 v = pf_mc[it];
            float4 a = sa4[j * (ACC_STRIDE / 4) + (IDIM / 4) + d4];
            v.x += a.x; v.y += a.y; v.z += a.z; v.w += a.w;
            o4[i] = v;
        }
    }
}

// ---------------------------------------------------------------------------
extern "C" void kernel_launch(void* const* d_in, const int* in_sizes, int n_in,
                              void* d_out, int out_size) {
    const float* ia = (const float*)d_in[0];
    const float* mc = (const float*)d_in[1];
    const float* qf = (const float*)d_in[2];
    const float* ap = (const float*)d_in[3];
    const int*   aq = (const int*)  d_in[4];
    const float* Wi = (const float*)d_in[5];
    const float* bi = (const float*)d_in[6];
    const float* Wm = (const float*)d_in[7];
    const float* bm = (const float*)d_in[8];

    cudaFuncSetAttribute(entity_kernel,
                         cudaFuncAttributeMaxDynamicSharedMemorySize, SMEM_BYTES);

    qproj_kernel<<<NBT * NQ, 256>>>(qf, Wi, bi, Wm, bm);
    entity_kernel<<<NBLK, TPB, SMEM_BYTES>>>(ia, mc, ap, aq, (float*)d_out);
}